// round 9
// baseline (speedup 1.0000x reference)
#include <cuda_runtime.h>
#include <cuda_fp16.h>

#define IN_DIM 256
#define OUT_DIM 128
#define MAX_NODES 100000
#define MAX_EDGES 3200000

// Scratch (device globals = allowed scratch).
__device__ __half g_h[(size_t)MAX_NODES * OUT_DIM];       // 25.6 MB fp16 h
__device__ int    g_deg[MAX_NODES];                       // per-dst edge count
__device__ int    g_off[MAX_NODES];                       // CSR start offsets
__device__ int    g_cur[MAX_NODES];                       // fill cursors
__device__ int    g_src_sorted[MAX_EDGES];                // src per slot
__device__ float  g_val_sorted[MAX_EDGES];                // val per slot

// ---- packed dual-fp32 helpers (Blackwell FFMA2; PTX-only path) -------------
__device__ __forceinline__ unsigned long long pack2(float lo, float hi) {
    unsigned long long r;
    asm("mov.b64 %0, {%1, %2};" : "=l"(r) : "f"(lo), "f"(hi));
    return r;
}
__device__ __forceinline__ void unpack2(unsigned long long p, float& lo, float& hi) {
    asm("mov.b64 {%0, %1}, %2;" : "=f"(lo), "=f"(hi) : "l"(p));
}
__device__ __forceinline__ void fma2(unsigned long long& acc,
                                     unsigned long long a, unsigned long long b) {
    asm("fma.rn.f32x2 %0, %1, %2, %0;" : "+l"(acc) : "l"(a), "l"(b));
}

// ---------------------------------------------------------------------------
// Kernel 1: tiled fp32 GEMM  h[M,128] = X[M,256] @ W[256,128]  (fp16 out)
// BM=128, BN=128, BK=16, 256 threads, 8x8 register tile, FFMA2 inner product.
// ---------------------------------------------------------------------------
__global__ __launch_bounds__(256, 2) void gemm_kernel(const float* __restrict__ X,
                                                      const float* __restrict__ W,
                                                      int M) {
    __shared__ float As[2][16][128];
    __shared__ float Bs[2][16][128];

    const int tid = threadIdx.x;
    const int tx = tid & 15;
    const int ty = tid >> 4;
    const int rowBase = blockIdx.x * 128;

    const int ar0 = tid >> 2;
    const int ar1 = (tid + 256) >> 2;
    const int ac  = (tid & 3) * 4;
    const int br0 = tid >> 5;
    const int br1 = (tid + 256) >> 5;
    const int bc  = (tid & 31) * 4;

    const bool aok0 = (rowBase + ar0) < M;
    const bool aok1 = (rowBase + ar1) < M;
    const float* Xp0 = X + (size_t)(rowBase + ar0) * IN_DIM + ac;
    const float* Xp1 = X + (size_t)(rowBase + ar1) * IN_DIM + ac;
    const float* Wp0 = W + (size_t)br0 * OUT_DIM + bc;
    const float* Wp1 = W + (size_t)br1 * OUT_DIM + bc;

    unsigned long long acc2[8][4];
    #pragma unroll
    for (int i = 0; i < 8; i++)
        #pragma unroll
        for (int j = 0; j < 4; j++) acc2[i][j] = 0ull;

    float4 a0, a1, b0, b1;

    a0 = aok0 ? *(const float4*)(Xp0) : make_float4(0.f, 0.f, 0.f, 0.f);
    a1 = aok1 ? *(const float4*)(Xp1) : make_float4(0.f, 0.f, 0.f, 0.f);
    b0 = *(const float4*)(Wp0);
    b1 = *(const float4*)(Wp1);

    As[0][ac + 0][ar0] = a0.x; As[0][ac + 1][ar0] = a0.y;
    As[0][ac + 2][ar0] = a0.z; As[0][ac + 3][ar0] = a0.w;
    As[0][ac + 0][ar1] = a1.x; As[0][ac + 1][ar1] = a1.y;
    As[0][ac + 2][ar1] = a1.z; As[0][ac + 3][ar1] = a1.w;
    *(float4*)(&Bs[0][br0][bc]) = b0;
    *(float4*)(&Bs[0][br1][bc]) = b1;
    __syncthreads();

    const int NT = IN_DIM / 16;
    #pragma unroll 1
    for (int t = 0; t < NT; t++) {
        const int buf = t & 1;

        if (t + 1 < NT) {
            const int koff = (t + 1) * 16;
            a0 = aok0 ? *(const float4*)(Xp0 + koff) : make_float4(0.f, 0.f, 0.f, 0.f);
            a1 = aok1 ? *(const float4*)(Xp1 + koff) : make_float4(0.f, 0.f, 0.f, 0.f);
            b0 = *(const float4*)(Wp0 + (size_t)koff * OUT_DIM);
            b1 = *(const float4*)(Wp1 + (size_t)koff * OUT_DIM);
        }

        #pragma unroll
        for (int k = 0; k < 16; k++) {
            float ra[8], rb[8];
            #pragma unroll
            for (int i = 0; i < 8; i += 4)
                *(float4*)(&ra[i]) = *(const float4*)(&As[buf][k][ty * 8 + i]);
            *(float4*)(&rb[0]) = *(const float4*)(&Bs[buf][k][tx * 4]);
            *(float4*)(&rb[4]) = *(const float4*)(&Bs[buf][k][64 + tx * 4]);

            unsigned long long rbp[4], rap[8];
            #pragma unroll
            for (int j = 0; j < 4; j++) rbp[j] = pack2(rb[2 * j], rb[2 * j + 1]);
            #pragma unroll
            for (int i = 0; i < 8; i++) rap[i] = pack2(ra[i], ra[i]);

            #pragma unroll
            for (int i = 0; i < 8; i++)
                #pragma unroll
                for (int j = 0; j < 4; j++)
                    fma2(acc2[i][j], rap[i], rbp[j]);
        }

        if (t + 1 < NT) {
            const int nb = buf ^ 1;
            As[nb][ac + 0][ar0] = a0.x; As[nb][ac + 1][ar0] = a0.y;
            As[nb][ac + 2][ar0] = a0.z; As[nb][ac + 3][ar0] = a0.w;
            As[nb][ac + 0][ar1] = a1.x; As[nb][ac + 1][ar1] = a1.y;
            As[nb][ac + 2][ar1] = a1.z; As[nb][ac + 3][ar1] = a1.w;
            *(float4*)(&Bs[nb][br0][bc]) = b0;
            *(float4*)(&Bs[nb][br1][bc]) = b1;
            __syncthreads();
        }
    }

    #pragma unroll
    for (int i = 0; i < 8; i++) {
        int gr = rowBase + ty * 8 + i;
        if (gr < M) {
            float4 c0, c1;
            unpack2(acc2[i][0], c0.x, c0.y);
            unpack2(acc2[i][1], c0.z, c0.w);
            unpack2(acc2[i][2], c1.x, c1.y);
            unpack2(acc2[i][3], c1.z, c1.w);
            __half* row = g_h + (size_t)gr * OUT_DIM;
            *(__half2*)(row + tx * 4 + 0)      = __floats2half2_rn(c0.x, c0.y);
            *(__half2*)(row + tx * 4 + 2)      = __floats2half2_rn(c0.z, c0.w);
            *(__half2*)(row + 64 + tx * 4 + 0) = __floats2half2_rn(c1.x, c1.y);
            *(__half2*)(row + 64 + tx * 4 + 2) = __floats2half2_rn(c1.z, c1.w);
        }
    }
}

// ---------------------------------------------------------------------------
// CSR build: zero -> count -> scan -> fill
// ---------------------------------------------------------------------------
__global__ void zero_deg_kernel(int N) {
    int i = blockIdx.x * blockDim.x + threadIdx.x;
    if (i < N) g_deg[i] = 0;
}

__global__ void count_kernel(const int* __restrict__ dst, int E) {
    int i = blockIdx.x * blockDim.x + threadIdx.x;
    if (i < E) atomicAdd(&g_deg[dst[i]], 1);
}

// Single-block exclusive scan over g_deg -> g_off (and g_cur copy).
__global__ __launch_bounds__(1024) void scan_kernel(int N) {
    __shared__ int s[1024];
    const int tid = threadIdx.x;
    const int chunk = (N + 1023) / 1024;
    const int lo = tid * chunk;
    const int hi = min(lo + chunk, N);

    int sum = 0;
    for (int i = lo; i < hi; i++) sum += g_deg[i];
    s[tid] = sum;
    __syncthreads();

    // Hillis-Steele inclusive scan.
    #pragma unroll
    for (int d = 1; d < 1024; d <<= 1) {
        int t = (tid >= d) ? s[tid - d] : 0;
        __syncthreads();
        s[tid] += t;
        __syncthreads();
    }
    int run = (tid == 0) ? 0 : s[tid - 1];
    for (int i = lo; i < hi; i++) {
        g_off[i] = run;
        g_cur[i] = run;
        run += g_deg[i];
    }
}

__global__ void fill_kernel(const int* __restrict__ src,
                            const int* __restrict__ dst,
                            const float* __restrict__ vals, int E) {
    int i = blockIdx.x * blockDim.x + threadIdx.x;
    if (i < E) {
        int p = atomicAdd(&g_cur[dst[i]], 1);
        g_src_sorted[p] = src[i];
        g_val_sorted[p] = vals[i];
    }
}

// ---------------------------------------------------------------------------
// Aggregate: one warp per dst node. Registers accumulate 128 cols (4/lane);
// single write to out with fused bias. No atomics anywhere.
// ---------------------------------------------------------------------------
__global__ __launch_bounds__(256) void aggregate_kernel(float* __restrict__ out,
                                                        const float* __restrict__ b,
                                                        int N) {
    int node = (int)((blockIdx.x * (long long)blockDim.x + threadIdx.x) >> 5);
    const int lane = threadIdx.x & 31;
    if (node >= N) return;

    const int start = g_off[node];
    const int end = start + g_deg[node];

    float4 acc = make_float4(0.f, 0.f, 0.f, 0.f);

    int i = start;
    // 2-deep software pipeline for gather MLP.
    for (; i + 1 < end; i += 2) {
        int   s0 = g_src_sorted[i],     s1 = g_src_sorted[i + 1];
        float v0 = g_val_sorted[i],     v1 = g_val_sorted[i + 1];
        uint2 m0 = *(const uint2*)(g_h + (size_t)s0 * OUT_DIM + lane * 4);
        uint2 m1 = *(const uint2*)(g_h + (size_t)s1 * OUT_DIM + lane * 4);
        float2 p00 = __half22float2(*(const __half2*)&m0.x);
        float2 p01 = __half22float2(*(const __half2*)&m0.y);
        float2 p10 = __half22float2(*(const __half2*)&m1.x);
        float2 p11 = __half22float2(*(const __half2*)&m1.y);
        acc.x += v0 * p00.x + v1 * p10.x;
        acc.y += v0 * p00.y + v1 * p10.y;
        acc.z += v0 * p01.x + v1 * p11.x;
        acc.w += v0 * p01.y + v1 * p11.y;
    }
    if (i < end) {
        int   s0 = g_src_sorted[i];
        float v0 = g_val_sorted[i];
        uint2 m0 = *(const uint2*)(g_h + (size_t)s0 * OUT_DIM + lane * 4);
        float2 p00 = __half22float2(*(const __half2*)&m0.x);
        float2 p01 = __half22float2(*(const __half2*)&m0.y);
        acc.x += v0 * p00.x;
        acc.y += v0 * p00.y;
        acc.z += v0 * p01.x;
        acc.w += v0 * p01.y;
    }

    float4 bb = *(const float4*)(b + lane * 4);
    acc.x += bb.x; acc.y += bb.y; acc.z += bb.z; acc.w += bb.w;
    *(float4*)(out + (size_t)node * OUT_DIM + lane * 4) = acc;
}

// ---------------------------------------------------------------------------
extern "C" void kernel_launch(void* const* d_in, const int* in_sizes, int n_in,
                              void* d_out, int out_size) {
    const float* X     = (const float*)d_in[0];  // feature_map [N, 256]
    const int*   esrc  = (const int*)d_in[1];    // edge_src [E]
    const int*   edst  = (const int*)d_in[2];    // edge_dst [E]
    const float* evals = (const float*)d_in[3];  // edge_vals [E]
    const float* W     = (const float*)d_in[4];  // weights [256, 128]
    const float* b     = (const float*)d_in[5];  // bias [128]
    float* out = (float*)d_out;

    int M = in_sizes[0] / IN_DIM;   // N_NODES
    int E = in_sizes[1];            // N_EDGES
    int eb = (E + 255) / 256;

    // CSR build (independent of GEMM; stream-serial order is fine).
    zero_deg_kernel<<<(M + 255) / 256, 256>>>(M);
    count_kernel<<<eb, 256>>>(edst, E);
    scan_kernel<<<1, 1024>>>(M);
    fill_kernel<<<eb, 256>>>(esrc, edst, evals, E);

    // h = X @ W (fp16 out)
    gemm_kernel<<<(M + 127) / 128, 256>>>(X, W, M);

    // out[n] = sum_{e: dst=n} val_e * h[src_e] + b
    long long threads = (long long)M * 32;
    int blocks = (int)((threads + 255) / 256);
    aggregate_kernel<<<blocks, 256>>>(out, b, M);
}

// round 10
// speedup vs baseline: 1.0726x; 1.0726x over previous
#include <cuda_runtime.h>
#include <cuda_fp16.h>

#define IN_DIM 256
#define OUT_DIM 128
#define MAX_NODES 100000
#define MAX_EDGES 3200000

// Scratch (device globals = allowed scratch).
__device__ __half g_h[(size_t)MAX_NODES * OUT_DIM];   // 25.6 MB fp16 h
__device__ int    g_deg[MAX_NODES];                   // per-dst edge count
__device__ int    g_off[MAX_NODES];                   // CSR start offsets
__device__ int    g_cur[MAX_NODES];                   // fill cursors
__device__ int2   g_sv[MAX_EDGES];                    // fused (src, val_bits)

// ---- packed dual-fp32 helpers (Blackwell FFMA2; PTX-only path) -------------
__device__ __forceinline__ unsigned long long pack2(float lo, float hi) {
    unsigned long long r;
    asm("mov.b64 %0, {%1, %2};" : "=l"(r) : "f"(lo), "f"(hi));
    return r;
}
__device__ __forceinline__ void unpack2(unsigned long long p, float& lo, float& hi) {
    asm("mov.b64 {%0, %1}, %2;" : "=f"(lo), "=f"(hi) : "l"(p));
}
__device__ __forceinline__ void fma2(unsigned long long& acc,
                                     unsigned long long a, unsigned long long b) {
    asm("fma.rn.f32x2 %0, %1, %2, %0;" : "+l"(acc) : "l"(a), "l"(b));
}

// ---------------------------------------------------------------------------
// Kernel 1: tiled fp32 GEMM  h[M,128] = X[M,256] @ W[256,128]  (fp16 out)
// ---------------------------------------------------------------------------
__global__ __launch_bounds__(256, 2) void gemm_kernel(const float* __restrict__ X,
                                                      const float* __restrict__ W,
                                                      int M) {
    __shared__ float As[2][16][128];
    __shared__ float Bs[2][16][128];

    const int tid = threadIdx.x;
    const int tx = tid & 15;
    const int ty = tid >> 4;
    const int rowBase = blockIdx.x * 128;

    const int ar0 = tid >> 2;
    const int ar1 = (tid + 256) >> 2;
    const int ac  = (tid & 3) * 4;
    const int br0 = tid >> 5;
    const int br1 = (tid + 256) >> 5;
    const int bc  = (tid & 31) * 4;

    const bool aok0 = (rowBase + ar0) < M;
    const bool aok1 = (rowBase + ar1) < M;
    const float* Xp0 = X + (size_t)(rowBase + ar0) * IN_DIM + ac;
    const float* Xp1 = X + (size_t)(rowBase + ar1) * IN_DIM + ac;
    const float* Wp0 = W + (size_t)br0 * OUT_DIM + bc;
    const float* Wp1 = W + (size_t)br1 * OUT_DIM + bc;

    unsigned long long acc2[8][4];
    #pragma unroll
    for (int i = 0; i < 8; i++)
        #pragma unroll
        for (int j = 0; j < 4; j++) acc2[i][j] = 0ull;

    float4 a0, a1, b0, b1;

    a0 = aok0 ? *(const float4*)(Xp0) : make_float4(0.f, 0.f, 0.f, 0.f);
    a1 = aok1 ? *(const float4*)(Xp1) : make_float4(0.f, 0.f, 0.f, 0.f);
    b0 = *(const float4*)(Wp0);
    b1 = *(const float4*)(Wp1);

    As[0][ac + 0][ar0] = a0.x; As[0][ac + 1][ar0] = a0.y;
    As[0][ac + 2][ar0] = a0.z; As[0][ac + 3][ar0] = a0.w;
    As[0][ac + 0][ar1] = a1.x; As[0][ac + 1][ar1] = a1.y;
    As[0][ac + 2][ar1] = a1.z; As[0][ac + 3][ar1] = a1.w;
    *(float4*)(&Bs[0][br0][bc]) = b0;
    *(float4*)(&Bs[0][br1][bc]) = b1;
    __syncthreads();

    const int NT = IN_DIM / 16;
    #pragma unroll 1
    for (int t = 0; t < NT; t++) {
        const int buf = t & 1;

        if (t + 1 < NT) {
            const int koff = (t + 1) * 16;
            a0 = aok0 ? *(const float4*)(Xp0 + koff) : make_float4(0.f, 0.f, 0.f, 0.f);
            a1 = aok1 ? *(const float4*)(Xp1 + koff) : make_float4(0.f, 0.f, 0.f, 0.f);
            b0 = *(const float4*)(Wp0 + (size_t)koff * OUT_DIM);
            b1 = *(const float4*)(Wp1 + (size_t)koff * OUT_DIM);
        }

        #pragma unroll
        for (int k = 0; k < 16; k++) {
            float ra[8], rb[8];
            #pragma unroll
            for (int i = 0; i < 8; i += 4)
                *(float4*)(&ra[i]) = *(const float4*)(&As[buf][k][ty * 8 + i]);
            *(float4*)(&rb[0]) = *(const float4*)(&Bs[buf][k][tx * 4]);
            *(float4*)(&rb[4]) = *(const float4*)(&Bs[buf][k][64 + tx * 4]);

            unsigned long long rbp[4], rap[8];
            #pragma unroll
            for (int j = 0; j < 4; j++) rbp[j] = pack2(rb[2 * j], rb[2 * j + 1]);
            #pragma unroll
            for (int i = 0; i < 8; i++) rap[i] = pack2(ra[i], ra[i]);

            #pragma unroll
            for (int i = 0; i < 8; i++)
                #pragma unroll
                for (int j = 0; j < 4; j++)
                    fma2(acc2[i][j], rap[i], rbp[j]);
        }

        if (t + 1 < NT) {
            const int nb = buf ^ 1;
            As[nb][ac + 0][ar0] = a0.x; As[nb][ac + 1][ar0] = a0.y;
            As[nb][ac + 2][ar0] = a0.z; As[nb][ac + 3][ar0] = a0.w;
            As[nb][ac + 0][ar1] = a1.x; As[nb][ac + 1][ar1] = a1.y;
            As[nb][ac + 2][ar1] = a1.z; As[nb][ac + 3][ar1] = a1.w;
            *(float4*)(&Bs[nb][br0][bc]) = b0;
            *(float4*)(&Bs[nb][br1][bc]) = b1;
            __syncthreads();
        }
    }

    #pragma unroll
    for (int i = 0; i < 8; i++) {
        int gr = rowBase + ty * 8 + i;
        if (gr < M) {
            float4 c0, c1;
            unpack2(acc2[i][0], c0.x, c0.y);
            unpack2(acc2[i][1], c0.z, c0.w);
            unpack2(acc2[i][2], c1.x, c1.y);
            unpack2(acc2[i][3], c1.z, c1.w);
            __half* row = g_h + (size_t)gr * OUT_DIM;
            *(__half2*)(row + tx * 4 + 0)      = __floats2half2_rn(c0.x, c0.y);
            *(__half2*)(row + tx * 4 + 2)      = __floats2half2_rn(c0.z, c0.w);
            *(__half2*)(row + 64 + tx * 4 + 0) = __floats2half2_rn(c1.x, c1.y);
            *(__half2*)(row + 64 + tx * 4 + 2) = __floats2half2_rn(c1.z, c1.w);
        }
    }
}

// ---------------------------------------------------------------------------
// CSR build: zero -> count -> scan -> fill (fused int2 payload)
// ---------------------------------------------------------------------------
__global__ void zero_deg_kernel(int N) {
    int i = blockIdx.x * blockDim.x + threadIdx.x;
    if (i < N) g_deg[i] = 0;
}

__global__ void count_kernel(const int* __restrict__ dst, int E) {
    int i = blockIdx.x * blockDim.x + threadIdx.x;
    if (i < E) atomicAdd(&g_deg[dst[i]], 1);
}

__global__ __launch_bounds__(1024) void scan_kernel(int N) {
    __shared__ int s[1024];
    const int tid = threadIdx.x;
    const int chunk = (N + 1023) / 1024;
    const int lo = tid * chunk;
    const int hi = min(lo + chunk, N);

    int sum = 0;
    for (int i = lo; i < hi; i++) sum += g_deg[i];
    s[tid] = sum;
    __syncthreads();

    #pragma unroll
    for (int d = 1; d < 1024; d <<= 1) {
        int t = (tid >= d) ? s[tid - d] : 0;
        __syncthreads();
        s[tid] += t;
        __syncthreads();
    }
    int run = (tid == 0) ? 0 : s[tid - 1];
    for (int i = lo; i < hi; i++) {
        g_off[i] = run;
        g_cur[i] = run;
        run += g_deg[i];
    }
}

__global__ void fill_kernel(const int* __restrict__ src,
                            const int* __restrict__ dst,
                            const float* __restrict__ vals, int E) {
    int i = blockIdx.x * blockDim.x + threadIdx.x;
    if (i < E) {
        int p = atomicAdd(&g_cur[dst[i]], 1);
        g_sv[p] = make_int2(src[i], __float_as_int(vals[i]));
    }
}

// ---------------------------------------------------------------------------
// Aggregate: one warp per dst node, 4-deep gather pipeline, fused bias,
// single non-atomic write.
// ---------------------------------------------------------------------------
__global__ __launch_bounds__(256) void aggregate_kernel(float* __restrict__ out,
                                                        const float* __restrict__ b,
                                                        int N) {
    int node = (int)((blockIdx.x * (long long)blockDim.x + threadIdx.x) >> 5);
    const int lane = threadIdx.x & 31;
    if (node >= N) return;

    const int start = g_off[node];
    const int end = start + g_deg[node];

    float4 acc = make_float4(0.f, 0.f, 0.f, 0.f);

    int i = start;
    for (; i + 3 < end; i += 4) {
        int2 e0 = g_sv[i], e1 = g_sv[i + 1], e2 = g_sv[i + 2], e3 = g_sv[i + 3];
        uint2 m0 = *(const uint2*)(g_h + (size_t)e0.x * OUT_DIM + lane * 4);
        uint2 m1 = *(const uint2*)(g_h + (size_t)e1.x * OUT_DIM + lane * 4);
        uint2 m2 = *(const uint2*)(g_h + (size_t)e2.x * OUT_DIM + lane * 4);
        uint2 m3 = *(const uint2*)(g_h + (size_t)e3.x * OUT_DIM + lane * 4);
        float v0 = __int_as_float(e0.y), v1 = __int_as_float(e1.y);
        float v2 = __int_as_float(e2.y), v3 = __int_as_float(e3.y);
        float2 a0 = __half22float2(*(const __half2*)&m0.x);
        float2 b0f = __half22float2(*(const __half2*)&m0.y);
        float2 a1 = __half22float2(*(const __half2*)&m1.x);
        float2 b1f = __half22float2(*(const __half2*)&m1.y);
        float2 a2 = __half22float2(*(const __half2*)&m2.x);
        float2 b2f = __half22float2(*(const __half2*)&m2.y);
        float2 a3 = __half22float2(*(const __half2*)&m3.x);
        float2 b3f = __half22float2(*(const __half2*)&m3.y);
        acc.x += v0 * a0.x + v1 * a1.x + v2 * a2.x + v3 * a3.x;
        acc.y += v0 * a0.y + v1 * a1.y + v2 * a2.y + v3 * a3.y;
        acc.z += v0 * b0f.x + v1 * b1f.x + v2 * b2f.x + v3 * b3f.x;
        acc.w += v0 * b0f.y + v1 * b1f.y + v2 * b2f.y + v3 * b3f.y;
    }
    for (; i < end; i++) {
        int2 e0 = g_sv[i];
        uint2 m0 = *(const uint2*)(g_h + (size_t)e0.x * OUT_DIM + lane * 4);
        float v0 = __int_as_float(e0.y);
        float2 a0 = __half22float2(*(const __half2*)&m0.x);
        float2 b0f = __half22float2(*(const __half2*)&m0.y);
        acc.x += v0 * a0.x;
        acc.y += v0 * a0.y;
        acc.z += v0 * b0f.x;
        acc.w += v0 * b0f.y;
    }

    float4 bb = *(const float4*)(b + lane * 4);
    acc.x += bb.x; acc.y += bb.y; acc.z += bb.z; acc.w += bb.w;
    *(float4*)(out + (size_t)node * OUT_DIM + lane * 4) = acc;
}

// ---------------------------------------------------------------------------
// Launch: CSR chain forked onto a second stream, overlapped with GEMM.
// Stream/events created once on the first (non-captured) correctness call;
// the per-call GPU work is identical every call.
// ---------------------------------------------------------------------------
extern "C" void kernel_launch(void* const* d_in, const int* in_sizes, int n_in,
                              void* d_out, int out_size) {
    const float* X     = (const float*)d_in[0];  // feature_map [N, 256]
    const int*   esrc  = (const int*)d_in[1];    // edge_src [E]
    const int*   edst  = (const int*)d_in[2];    // edge_dst [E]
    const float* evals = (const float*)d_in[3];  // edge_vals [E]
    const float* W     = (const float*)d_in[4];  // weights [256, 128]
    const float* b     = (const float*)d_in[5];  // bias [128]
    float* out = (float*)d_out;

    int M = in_sizes[0] / IN_DIM;   // N_NODES
    int E = in_sizes[1];            // N_EDGES
    int eb = (E + 255) / 256;

    static cudaStream_t s2 = []() {
        cudaStream_t s;
        cudaStreamCreateWithFlags(&s, cudaStreamNonBlocking);
        return s;
    }();
    static cudaEvent_t evFork = []() {
        cudaEvent_t e;
        cudaEventCreateWithFlags(&e, cudaEventDisableTiming);
        return e;
    }();
    static cudaEvent_t evJoin = []() {
        cudaEvent_t e;
        cudaEventCreateWithFlags(&e, cudaEventDisableTiming);
        return e;
    }();

    // Fork: CSR build chain on s2, GEMM on the main (capture) stream.
    cudaEventRecord(evFork, 0);
    cudaStreamWaitEvent(s2, evFork, 0);

    zero_deg_kernel<<<(M + 255) / 256, 256, 0, s2>>>(M);
    count_kernel<<<eb, 256, 0, s2>>>(edst, E);
    scan_kernel<<<1, 1024, 0, s2>>>(M);
    fill_kernel<<<eb, 256, 0, s2>>>(esrc, edst, evals, E);
    cudaEventRecord(evJoin, s2);

    gemm_kernel<<<(M + 127) / 128, 256>>>(X, W, M);

    // Join: aggregate needs both CSR and h.
    cudaStreamWaitEvent(0, evJoin, 0);
    long long threads = (long long)M * 32;
    int blocks = (int)((threads + 255) / 256);
    aggregate_kernel<<<blocks, 256>>>(out, b, M);
}